// round 16
// baseline (speedup 1.0000x reference)
#include <cuda_runtime.h>
#include <cuda_bf16.h>
#include <cstdint>
#include <mma.h>

using namespace nvcuda;

// Problem shape (fixed by the dataset instance)
constexpr int B  = 256;
constexpr int S  = 128;
constexpr int H  = 768;
constexpr int D  = S * H;      // 98304

// GEMM tiling
constexpr int KC     = 64;                  // K elems per stage
constexpr int LDTF   = 68;                  // padded fp32 leading dim (floats)
constexpr int KSPLIT = 37;                  // 4*37 = 148 CTAs = one full wave
constexpr int STAGES = 3;
constexpr int TILE_FLOATS  = 128 * LDTF;    // one A (or B) stage tile
constexpr int STAGE_FLOATS = 2 * TILE_FLOATS;
constexpr size_t SMEM_BYTES = (size_t)STAGES * STAGE_FLOATS * 4;   // 208.9 KB

// Device scratch (allocation-free rule: __device__ globals)
__device__ float g_part[(size_t)KSPLIT * B * B];   // split-K partials (9.7 MB)
__device__ float g_s2p[KSPLIT * B];                // per-z row-norm partials (student)
__device__ float g_t2p[KSPLIT * B];                // per-z row-norm partials (teacher)
__device__ float g_acc = 0.f;                      // self-resetting accumulator
__device__ int   g_counter = 0;                    // self-resetting block counter

__device__ __forceinline__ void cp16(unsigned dst, const void* src) {
    asm volatile("cp.async.ca.shared.global [%0], [%1], 16;\n" :: "r"(dst), "l"(src));
}
__device__ __forceinline__ void cp_commit() {
    asm volatile("cp.async.commit_group;\n");
}
__device__ __forceinline__ void cp_wait1() {
    asm volatile("cp.async.wait_group 1;\n" ::: "memory");
}
__device__ __forceinline__ void cp_wait0() {
    asm volatile("cp.async.wait_group 0;\n" ::: "memory");
}

__inline__ __device__ float block_reduce_sum(float v) {
    __shared__ float sm[32];
    for (int o = 16; o > 0; o >>= 1) v += __shfl_down_sync(0xffffffffu, v, o);
    int lane = threadIdx.x & 31, w = threadIdx.x >> 5;
    if (lane == 0) sm[w] = v;
    __syncthreads();
    int nw = (blockDim.x + 31) >> 5;
    if (w == 0) {
        v = (lane < nw) ? sm[lane] : 0.f;
        for (int o = 16; o > 0; o >>= 1) v += __shfl_down_sync(0xffffffffu, v, o);
    }
    __syncthreads();
    return v;  // valid on thread 0
}

// 3-stage cp.async pipelined split-K TF32 GEMM on raw fp32 + fused row norms.
// part[z][i][j] = sum_{k in slice z} tf32(sf[i][k]) * tf32(tf[j][k])  (fp32 accum)
__global__ void __launch_bounds__(256) gemm_kernel(const float* __restrict__ s_feat,
                                                   const float* __restrict__ t_feat) {
    extern __shared__ float smem[];

    const int m0 = blockIdx.x * 128;
    const int n0 = blockIdx.y * 128;
    const int z  = blockIdx.z;
    int it0, niter;
    if (z < 19) { niter = 42; it0 = z * 42; }
    else        { niter = 41; it0 = 798 + (z - 19) * 41; }

    const int tid = threadIdx.x, warp = tid >> 5, lane = tid & 31;
    const int wm = warp & 3;   // 4 warps across M (32 rows each)
    const int wn = warp >> 2;  // 2 warps across N (64 cols each)
    const bool doA = (blockIdx.y == 0);
    const bool doB = (blockIdx.x == 0);

    unsigned smem_base;
    asm("{.reg .u64 t; cvta.to.shared.u64 t, %1; cvt.u32.u64 %0, t;}"
        : "=r"(smem_base) : "l"(smem));

#define ISSUE(ITv, Sv) do {                                                        \
        const size_t k0_ = (size_t)(it0 + (ITv)) * KC;                             \
        unsigned sA_ = smem_base + (unsigned)((Sv) * STAGE_FLOATS) * 4u;           \
        unsigned sB_ = sA_ + (unsigned)TILE_FLOATS * 4u;                           \
        _Pragma("unroll")                                                          \
        for (int u = 0; u < 8; u++) {                                              \
            int idx = tid + 256 * u;              /* 0..2047 */                    \
            int row = idx >> 4, seg = idx & 15;                                    \
            cp16(sA_ + (unsigned)(row * LDTF + seg * 4) * 4u,                      \
                 s_feat + (size_t)(m0 + row) * D + k0_ + seg * 4);                 \
            cp16(sB_ + (unsigned)(row * LDTF + seg * 4) * 4u,                      \
                 t_feat + (size_t)(n0 + row) * D + k0_ + seg * 4);                 \
        }                                                                          \
        cp_commit();                                                               \
    } while (0)

    wmma::fragment<wmma::accumulator, 16, 16, 8, float> acc[2][4];
#pragma unroll
    for (int i = 0; i < 2; i++)
#pragma unroll
        for (int j = 0; j < 4; j++) wmma::fill_fragment(acc[i][j], 0.f);

    float nA = 0.f, nB = 0.f;   // this thread covers row tid>>1, half tid&1

    ISSUE(0, 0);
    ISSUE(1, 1);

    for (int it = 0; it < niter; ++it) {
        const int s = it % 3;
        if (it + 1 < niter) cp_wait1(); else cp_wait0();
        __syncthreads();                       // stage s visible; prev MMA done
        if (it + 2 < niter) ISSUE(it + 2, (it + 2) % 3);

        const float* As = smem + s * STAGE_FLOATS;
        const float* Bs = As + TILE_FLOATS;

        // fused row norms from the fp32 stage (2 threads per row)
        if (doA) {
            const float* p = As + (tid >> 1) * LDTF + (tid & 1) * 32;
#pragma unroll
            for (int q = 0; q < 32; q++) nA += p[q] * p[q];
        }
        if (doB) {
            const float* p = Bs + (tid >> 1) * LDTF + (tid & 1) * 32;
#pragma unroll
            for (int q = 0; q < 32; q++) nB += p[q] * p[q];
        }

#pragma unroll
        for (int kk = 0; kk < KC; kk += 8) {
            wmma::fragment<wmma::matrix_a, 16, 16, 8, wmma::precision::tf32,
                           wmma::row_major> af[2];
            wmma::fragment<wmma::matrix_b, 16, 16, 8, wmma::precision::tf32,
                           wmma::col_major> bf[4];
#pragma unroll
            for (int i = 0; i < 2; i++) {
                wmma::load_matrix_sync(af[i], As + (wm * 32 + i * 16) * LDTF + kk, LDTF);
#pragma unroll
                for (int t = 0; t < af[i].num_elements; t++)
                    af[i].x[t] = wmma::__float_to_tf32(af[i].x[t]);
            }
#pragma unroll
            for (int j = 0; j < 4; j++) {
                wmma::load_matrix_sync(bf[j], Bs + (wn * 64 + j * 16) * LDTF + kk, LDTF);
#pragma unroll
                for (int t = 0; t < bf[j].num_elements; t++)
                    bf[j].x[t] = wmma::__float_to_tf32(bf[j].x[t]);
            }
#pragma unroll
            for (int i = 0; i < 2; i++)
#pragma unroll
                for (int j = 0; j < 4; j++)
                    wmma::mma_sync(acc[i][j], af[i], bf[j], acc[i][j]);
        }
    }
#undef ISSUE

    // norm partials: pair-reduce (threads 2r, 2r+1), plain stores
    nA += __shfl_xor_sync(0xffffffffu, nA, 1);
    nB += __shfl_xor_sync(0xffffffffu, nB, 1);
    if ((tid & 1) == 0) {
        if (doA) g_s2p[z * B + m0 + (tid >> 1)] = nA;
        if (doB) g_t2p[z * B + n0 + (tid >> 1)] = nB;
    }

    // epilogue: plain stores of this z-slice's partials
    float* base = g_part + (size_t)z * B * B;
#pragma unroll
    for (int i = 0; i < 2; i++)
#pragma unroll
        for (int j = 0; j < 4; j++) {
            const int r0 = m0 + wm * 32 + i * 16;
            const int c0 = n0 + wn * 64 + j * 16;
            wmma::store_matrix_sync(base + (size_t)r0 * B + c0, acc[i][j], B,
                                    wmma::mem_row_major);
        }
}

// One block per row i (grid=256): thread j reduces its own z-column of g_part,
// builds the masked sq row in smem; warp 0 runs the shfl top-k; the last block
// also computes the logit losses and writes all outputs.
__global__ void __launch_bounds__(256) topk_kernel(const int* __restrict__ labels,
                                                   const int* __restrict__ kptr,
                                                   const float* __restrict__ t_logits,
                                                   const float* __restrict__ s_logits,
                                                   const int* __restrict__ tptr,
                                                   float* __restrict__ out) {
    const int i = blockIdx.x;
    const int j = threadIdx.x;
    const int lane = j & 31, warp = j >> 5;
    const float BIG = 3e38f;

    float dot = 0.f, t2 = 0.f;
#pragma unroll 4
    for (int z = 0; z < KSPLIT; z++) {
        dot += g_part[(size_t)z * B * B + (size_t)i * B + j];
        t2  += g_t2p[z * B + j];
    }
    float s2part = (j < KSPLIT) ? g_s2p[j * B + i] : 0.f;
    __shared__ float s2red[64];
    if (j < 64) s2red[j] = 0.f;
    __syncthreads();
    if (j < KSPLIT) s2red[j] = s2part;
    __syncthreads();
    __shared__ float s2sh;
    __shared__ int lish;
    if (j == 0) {
        float s = 0.f;
#pragma unroll
        for (int z = 0; z < 64; z++) s += s2red[z];
        s2sh = s;
        lish = labels[i];
    }
    __syncthreads();
    const float s2i = s2sh;
    const int li = lish;

    __shared__ float sq[B];
    sq[j] = (labels[j] == li) ? fmaxf(s2i + t2 - 2.f * dot, 0.f) : BIG;
    __syncthreads();

    __shared__ float blocksum;
    if (warp == 0) {
        float v[8];
#pragma unroll
        for (int t = 0; t < 8; t++) v[t] = sq[lane + 32 * t];

        int k = kptr ? kptr[0] : 5;
        if (k > B) k = B;
        if (k < 0) k = 0;

        float ssum = 0.f;
        for (int r = 0; r < k; ++r) {
            float m = v[0];
#pragma unroll
            for (int t = 1; t < 8; t++) m = fminf(m, v[t]);
#pragma unroll
            for (int off = 16; off > 0; off >>= 1)
                m = fminf(m, __shfl_xor_sync(0xffffffffu, m, off));
            if (m >= 1e37f) break;  // fewer than k same-label entries
            bool has = false;
#pragma unroll
            for (int t = 0; t < 8; t++) has |= (v[t] == m);
            unsigned bal = __ballot_sync(0xffffffffu, has);
            int win = __ffs(bal) - 1;
            if (lane == win) {
                bool done = false;
#pragma unroll
                for (int t = 0; t < 8; t++)
                    if (!done && v[t] == m) { v[t] = BIG; done = true; }
            }
            if (lane == 0) ssum += m;
        }
        if (lane == 0) blocksum = ssum;
    }
    __syncthreads();

    __shared__ float sh_total;
    __shared__ int   sh_last;
    if (j == 0) {
        atomicAdd(&g_acc, blocksum);
        __threadfence();
        int c = atomicAdd(&g_counter, 1);
        if (c == (int)gridDim.x - 1) {
            sh_total  = atomicAdd(&g_acc, 0.f);  // all adds visible (fenced before counter)
            sh_last   = 1;
            g_counter = 0;   // self-reset for next graph replay
            g_acc     = 0.f;
        } else {
            sh_last = 0;
        }
    }
    __syncthreads();

    if (sh_last) {
        const int b = threadIdx.x;
        const float T = tptr ? (float)tptr[0] : 4.f;

        float s0 = s_logits[2 * b], s1 = s_logits[2 * b + 1];
        float m = fmaxf(s0, s1);
        float lse = m + logf(expf(s0 - m) + expf(s1 - m));
        int lab = labels[b];
        float tr = lse - (lab ? s1 : s0);

        float t0 = t_logits[2 * b] / T, t1 = t_logits[2 * b + 1] / T;
        float mt = fmaxf(t0, t1);
        float e0 = expf(t0 - mt), e1 = expf(t1 - mt);
        float Z = e0 + e1;
        float p0 = e0 / Z, p1 = e1 / Z;
        float q0 = s0 / T, q1 = s1 / T;
        float mq = fmaxf(q0, q1);
        float lseq = mq + logf(expf(q0 - mq) + expf(q1 - mq));
        float soft = p0 * (logf(p0) - (q0 - lseq)) + p1 * (logf(p1) - (q1 - lseq));

        float trs = block_reduce_sum(tr);
        float sfs = block_reduce_sum(soft);
        if (b == 0) {
            out[0] = trs / (float)B;
            out[1] = sfs / (float)B * T * T;
            out[2] = sh_total / (float)D;
        }
    }
}

extern "C" void kernel_launch(void* const* d_in, const int* in_sizes, int n_in,
                              void* d_out, int out_size) {
    const float* t_logits = (const float*)d_in[0];
    const float* s_logits = (const float*)d_in[1];
    const float* t_feat   = (const float*)d_in[2];
    const float* s_feat   = (const float*)d_in[3];
    const int*   labels   = (const int*)d_in[4];            // int32 (JAX x64 disabled)
    const int*   kptr     = (n_in > 5) ? (const int*)d_in[5] : nullptr;
    const int*   tptr     = (n_in > 6) ? (const int*)d_in[6] : nullptr;
    float* out = (float*)d_out;

    cudaFuncSetAttribute(gemm_kernel, cudaFuncAttributeMaxDynamicSharedMemorySize,
                         (int)SMEM_BYTES);
    gemm_kernel<<<dim3(2, 2, KSPLIT), 256, SMEM_BYTES>>>(s_feat, t_feat);
    topk_kernel<<<B, 256>>>(labels, kptr, t_logits, s_logits, tptr, out);
}

// round 17
// speedup vs baseline: 2.6202x; 2.6202x over previous
#include <cuda_runtime.h>
#include <cuda_bf16.h>
#include <cstdint>
#include <mma.h>

using namespace nvcuda;

// Problem shape (fixed by the dataset instance)
constexpr int B  = 256;
constexpr int S  = 128;
constexpr int H  = 768;
constexpr int D  = S * H;      // 98304

// GEMM tiling
constexpr int KC     = 64;                 // K elems staged per iteration
constexpr int LDT    = 72;                 // padded smem leading dim (bf16 elems)
constexpr int KSPLIT = 37;                 // 4*37 = 148 CTAs = one full wave

// Device scratch (allocation-free rule: __device__ globals)
__device__ float g_part[(size_t)KSPLIT * B * B];   // split-K partials (9.7 MB)
__device__ float g_s2p[KSPLIT * B];                // per-z row-norm partials (student)
__device__ float g_t2p[KSPLIT * B];                // per-z row-norm partials (teacher)
__device__ float g_acc = 0.f;                      // self-resetting accumulator
__device__ int   g_counter = 0;                    // self-resetting block counter

__inline__ __device__ float block_reduce_sum(float v) {
    __shared__ float sm[32];
    for (int o = 16; o > 0; o >>= 1) v += __shfl_down_sync(0xffffffffu, v, o);
    int lane = threadIdx.x & 31, w = threadIdx.x >> 5;
    if (lane == 0) sm[w] = v;
    __syncthreads();
    int nw = (blockDim.x + 31) >> 5;
    if (w == 0) {
        v = (lane < nw) ? sm[lane] : 0.f;
        for (int o = 16; o > 0; o >>= 1) v += __shfl_down_sync(0xffffffffu, v, o);
    }
    __syncthreads();
    return v;  // valid on thread 0
}

// Fused fp32->bf16 + split-K bf16 wmma GEMM + row-norm partials.
// 512 threads (16 warps, 4 per SMSP) for latency hiding; register prefetch
// pipeline: next tile's LDGs issued before the MMA section.
__global__ void __launch_bounds__(512) gemm_kernel(const float* __restrict__ s_feat,
                                                   const float* __restrict__ t_feat) {
    __shared__ __nv_bfloat16 smA[128 * LDT];
    __shared__ __nv_bfloat16 smB[128 * LDT];

    const int m0 = blockIdx.x * 128;
    const int n0 = blockIdx.y * 128;
    const int z  = blockIdx.z;
    int it0, niter;
    if (z < 19) { niter = 42; it0 = z * 42; }
    else        { niter = 41; it0 = 798 + (z - 19) * 41; }

    const int tid = threadIdx.x, warp = tid >> 5, lane = tid & 31;
    const int wm = warp & 3;   // 4 warps across M (32 rows each)
    const int wn = warp >> 2;  // 4 warps across N (32 cols each)

    const int row0 = tid >> 3;       // 0..63 (row = row0 + 64*u)
    const int seg  = tid & 7;        // 8 segs x 8 floats = KC
    const size_t aoff = (size_t)(m0 + row0) * D + seg * 8;
    const size_t boff = (size_t)(n0 + row0) * D + seg * 8;

    float4 bA[4], bB[4];             // register prefetch buffers (16+16 floats)
    float nA[2] = {0.f, 0.f};
    float nB[2] = {0.f, 0.f};

    wmma::fragment<wmma::accumulator, 16, 16, 16, float> acc[2][2];
#pragma unroll
    for (int i = 0; i < 2; i++)
#pragma unroll
        for (int j = 0; j < 2; j++) wmma::fill_fragment(acc[i][j], 0.f);

#define PREFETCH(K0) do {                                                       \
        _Pragma("unroll")                                                       \
        for (int u = 0; u < 2; u++) {                                           \
            const float4* pa = (const float4*)(s_feat + aoff + (size_t)(64 * u) * D + (K0)); \
            bA[2 * u] = pa[0]; bA[2 * u + 1] = pa[1];                           \
            const float4* pb = (const float4*)(t_feat + boff + (size_t)(64 * u) * D + (K0)); \
            bB[2 * u] = pb[0]; bB[2 * u + 1] = pb[1];                           \
        }                                                                       \
    } while (0)

    PREFETCH((size_t)it0 * KC);

    for (int it = 0; it < niter; ++it) {
        // stage registers -> smem (convert to bf16, accumulate norms)
#pragma unroll
        for (int u = 0; u < 2; u++) {
            const int row = row0 + 64 * u;
            float4 a0 = bA[2 * u], a1 = bA[2 * u + 1];
            nA[u] += a0.x * a0.x + a0.y * a0.y + a0.z * a0.z + a0.w * a0.w
                   + a1.x * a1.x + a1.y * a1.y + a1.z * a1.z + a1.w * a1.w;
            __nv_bfloat162 h0 = __float22bfloat162_rn(make_float2(a0.x, a0.y));
            __nv_bfloat162 h1 = __float22bfloat162_rn(make_float2(a0.z, a0.w));
            __nv_bfloat162 h2 = __float22bfloat162_rn(make_float2(a1.x, a1.y));
            __nv_bfloat162 h3 = __float22bfloat162_rn(make_float2(a1.z, a1.w));
            uint4 wA;
            wA.x = *reinterpret_cast<unsigned*>(&h0);
            wA.y = *reinterpret_cast<unsigned*>(&h1);
            wA.z = *reinterpret_cast<unsigned*>(&h2);
            wA.w = *reinterpret_cast<unsigned*>(&h3);
            *(uint4*)&smA[row * LDT + seg * 8] = wA;

            float4 b0 = bB[2 * u], b1 = bB[2 * u + 1];
            nB[u] += b0.x * b0.x + b0.y * b0.y + b0.z * b0.z + b0.w * b0.w
                   + b1.x * b1.x + b1.y * b1.y + b1.z * b1.z + b1.w * b1.w;
            __nv_bfloat162 g0 = __float22bfloat162_rn(make_float2(b0.x, b0.y));
            __nv_bfloat162 g1 = __float22bfloat162_rn(make_float2(b0.z, b0.w));
            __nv_bfloat162 g2 = __float22bfloat162_rn(make_float2(b1.x, b1.y));
            __nv_bfloat162 g3 = __float22bfloat162_rn(make_float2(b1.z, b1.w));
            uint4 wB;
            wB.x = *reinterpret_cast<unsigned*>(&g0);
            wB.y = *reinterpret_cast<unsigned*>(&g1);
            wB.z = *reinterpret_cast<unsigned*>(&g2);
            wB.w = *reinterpret_cast<unsigned*>(&g3);
            *(uint4*)&smB[row * LDT + seg * 8] = wB;
        }
        __syncthreads();

        // issue next tile's loads BEFORE the MMA section (latency hidden by MMA)
        if (it + 1 < niter) PREFETCH((size_t)(it0 + it + 1) * KC);

#pragma unroll
        for (int kk = 0; kk < KC; kk += 16) {
            wmma::fragment<wmma::matrix_a, 16, 16, 16, __nv_bfloat16, wmma::row_major> af[2];
            wmma::fragment<wmma::matrix_b, 16, 16, 16, __nv_bfloat16, wmma::col_major> bf[2];
#pragma unroll
            for (int i = 0; i < 2; i++)
                wmma::load_matrix_sync(af[i], &smA[(wm * 32 + i * 16) * LDT + kk], LDT);
#pragma unroll
            for (int j = 0; j < 2; j++)
                wmma::load_matrix_sync(bf[j], &smB[(wn * 32 + j * 16) * LDT + kk], LDT);
#pragma unroll
            for (int i = 0; i < 2; i++)
#pragma unroll
                for (int j = 0; j < 2; j++)
                    wmma::mma_sync(acc[i][j], af[i], bf[j], acc[i][j]);
        }
        __syncthreads();
    }
#undef PREFETCH

    // Row-norm partials: 8 consecutive lanes share one row; plain stores (no atomics).
#pragma unroll
    for (int u = 0; u < 2; u++) {
        const int row = row0 + 64 * u;
        float va = nA[u];
        va += __shfl_down_sync(0xffffffffu, va, 4, 8);
        va += __shfl_down_sync(0xffffffffu, va, 2, 8);
        va += __shfl_down_sync(0xffffffffu, va, 1, 8);
        if ((lane & 7) == 0 && blockIdx.y == 0) g_s2p[z * B + m0 + row] = va;
        float vb = nB[u];
        vb += __shfl_down_sync(0xffffffffu, vb, 4, 8);
        vb += __shfl_down_sync(0xffffffffu, vb, 2, 8);
        vb += __shfl_down_sync(0xffffffffu, vb, 1, 8);
        if ((lane & 7) == 0 && blockIdx.x == 0) g_t2p[z * B + n0 + row] = vb;
    }

    // Epilogue: plain stores of this z-slice's partials
    float* base = g_part + (size_t)z * B * B;
#pragma unroll
    for (int i = 0; i < 2; i++)
#pragma unroll
        for (int j = 0; j < 2; j++) {
            const int r0 = m0 + wm * 32 + i * 16;
            const int c0 = n0 + wn * 32 + j * 16;
            wmma::store_matrix_sync(base + (size_t)r0 * B + c0, acc[i][j], B,
                                    wmma::mem_row_major);
        }
}

// One block per row i (grid=256): thread j reduces its own z-column of g_part,
// builds the masked sq row in smem; warp 0 runs the shfl top-k; the last block
// also computes the logit losses and writes all outputs.
__global__ void __launch_bounds__(256) topk_kernel(const int* __restrict__ labels,
                                                   const int* __restrict__ kptr,
                                                   const float* __restrict__ t_logits,
                                                   const float* __restrict__ s_logits,
                                                   const int* __restrict__ tptr,
                                                   float* __restrict__ out) {
    const int i = blockIdx.x;
    const int j = threadIdx.x;
    const int lane = j & 31, warp = j >> 5;
    const float BIG = 3e38f;

    float dot = 0.f, t2 = 0.f;
#pragma unroll 4
    for (int z = 0; z < KSPLIT; z++) {
        dot += g_part[(size_t)z * B * B + (size_t)i * B + j];
        t2  += g_t2p[z * B + j];
    }
    float s2part = (j < KSPLIT) ? g_s2p[j * B + i] : 0.f;
    __shared__ float s2red[64];
    if (j < 64) s2red[j] = 0.f;
    __syncthreads();
    if (j < KSPLIT) s2red[j] = s2part;
    __syncthreads();
    __shared__ float s2sh;
    __shared__ int lish;
    if (j == 0) {
        float s = 0.f;
#pragma unroll
        for (int z = 0; z < 64; z++) s += s2red[z];
        s2sh = s;
        lish = labels[i];
    }
    __syncthreads();
    const float s2i = s2sh;
    const int li = lish;

    __shared__ float sq[B];
    sq[j] = (labels[j] == li) ? fmaxf(s2i + t2 - 2.f * dot, 0.f) : BIG;
    __syncthreads();

    __shared__ float blocksum;
    if (warp == 0) {
        float v[8];
#pragma unroll
        for (int t = 0; t < 8; t++) v[t] = sq[lane + 32 * t];

        int k = kptr ? kptr[0] : 5;
        if (k > B) k = B;
        if (k < 0) k = 0;

        float ssum = 0.f;
        for (int r = 0; r < k; ++r) {
            float m = v[0];
#pragma unroll
            for (int t = 1; t < 8; t++) m = fminf(m, v[t]);
#pragma unroll
            for (int off = 16; off > 0; off >>= 1)
                m = fminf(m, __shfl_xor_sync(0xffffffffu, m, off));
            if (m >= 1e37f) break;  // fewer than k same-label entries
            bool has = false;
#pragma unroll
            for (int t = 0; t < 8; t++) has |= (v[t] == m);
            unsigned bal = __ballot_sync(0xffffffffu, has);
            int win = __ffs(bal) - 1;
            if (lane == win) {
                bool done = false;
#pragma unroll
                for (int t = 0; t < 8; t++)
                    if (!done && v[t] == m) { v[t] = BIG; done = true; }
            }
            if (lane == 0) ssum += m;
        }
        if (lane == 0) blocksum = ssum;
    }
    __syncthreads();

    __shared__ float sh_total;
    __shared__ int   sh_last;
    if (j == 0) {
        atomicAdd(&g_acc, blocksum);
        __threadfence();
        int c = atomicAdd(&g_counter, 1);
        if (c == (int)gridDim.x - 1) {
            sh_total  = atomicAdd(&g_acc, 0.f);  // all adds visible (fenced before counter)
            sh_last   = 1;
            g_counter = 0;   // self-reset for next graph replay
            g_acc     = 0.f;
        } else {
            sh_last = 0;
        }
    }
    __syncthreads();

    if (sh_last) {
        const int b = threadIdx.x;
        const float T = tptr ? (float)tptr[0] : 4.f;

        float s0 = s_logits[2 * b], s1 = s_logits[2 * b + 1];
        float m = fmaxf(s0, s1);
        float lse = m + logf(expf(s0 - m) + expf(s1 - m));
        int lab = labels[b];
        float tr = lse - (lab ? s1 : s0);

        float t0 = t_logits[2 * b] / T, t1 = t_logits[2 * b + 1] / T;
        float mt = fmaxf(t0, t1);
        float e0 = expf(t0 - mt), e1 = expf(t1 - mt);
        float Z = e0 + e1;
        float p0 = e0 / Z, p1 = e1 / Z;
        float q0 = s0 / T, q1 = s1 / T;
        float mq = fmaxf(q0, q1);
        float lseq = mq + logf(expf(q0 - mq) + expf(q1 - mq));
        float soft = p0 * (logf(p0) - (q0 - lseq)) + p1 * (logf(p1) - (q1 - lseq));

        float trs = block_reduce_sum(tr);
        float sfs = block_reduce_sum(soft);
        if (b == 0) {
            out[0] = trs / (float)B;
            out[1] = sfs / (float)B * T * T;
            out[2] = sh_total / (float)D;
        }
    }
}

extern "C" void kernel_launch(void* const* d_in, const int* in_sizes, int n_in,
                              void* d_out, int out_size) {
    const float* t_logits = (const float*)d_in[0];
    const float* s_logits = (const float*)d_in[1];
    const float* t_feat   = (const float*)d_in[2];
    const float* s_feat   = (const float*)d_in[3];
    const int*   labels   = (const int*)d_in[4];            // int32 (JAX x64 disabled)
    const int*   kptr     = (n_in > 5) ? (const int*)d_in[5] : nullptr;
    const int*   tptr     = (n_in > 6) ? (const int*)d_in[6] : nullptr;
    float* out = (float*)d_out;

    gemm_kernel<<<dim3(2, 2, KSPLIT), 512>>>(s_feat, t_feat);
    topk_kernel<<<B, 256>>>(labels, kptr, t_logits, s_logits, tptr, out);
}